// round 5
// baseline (speedup 1.0000x reference)
#include <cuda_runtime.h>
#include <cuda_bf16.h>

// Top1Router: inputs [8192, 64] fp32.
// capacity = max(even(floor(1.25*8192/64)), 4) = 160
// Output (fp32, concatenated): combine_weights [T,E,C] then sec_mask [T,E,C].
// Strategy: parallel route -> cudaMemsetAsync (fastest measured bulk zero)
//           -> parallel sparse scatter of the <=16384 nonzeros.

#define T_TOKENS  8192
#define N_EXP     64
#define CAPACITY  160
#define ROW_FLOATS (N_EXP * CAPACITY)               // 10240
#define C1 ((long long)T_TOKENS * ROW_FLOATS)       // 83,886,080
#define N_CHUNKS   8                                // 8 x 1024 tokens

__device__ int   g_top1[T_TOKENS];
__device__ float g_prob[T_TOKENS];
__device__ int   g_rankpart[T_TOKENS];              // within-chunk rank
__device__ int   g_cnt[N_CHUNKS][N_EXP];            // per-chunk per-expert counts

// ---------------------------------------------------------------------------
// Kernel 1: route. 8 CTAs x 1024 threads, thread-per-token.
// argmax (first-index tie-break) + softmax prob of top-1, then within-chunk
// stable rank via __match_any + per-warp hist + 64-thread scan.
// ---------------------------------------------------------------------------
__global__ void __launch_bounds__(1024) route_kernel(const float* __restrict__ x) {
    __shared__ int hist[32][N_EXP];

    int tid  = threadIdx.x;
    int wid  = tid >> 5;
    int lane = tid & 31;
    int t    = blockIdx.x * 1024 + tid;

    const float4* row = (const float4*)(x + (size_t)t * N_EXP);

    // max + argmax (strict > keeps lowest index on ties, matching jnp.argmax)
    float m = -__FLT_MAX__;
    int   e = 0;
    #pragma unroll
    for (int i = 0; i < 16; i++) {
        float4 v = row[i];
        if (v.x > m) { m = v.x; e = 4 * i + 0; }
        if (v.y > m) { m = v.y; e = 4 * i + 1; }
        if (v.z > m) { m = v.z; e = 4 * i + 2; }
        if (v.w > m) { m = v.w; e = 4 * i + 3; }
    }
    // sum of exp(x - max): softmax prob at argmax = 1/s
    float s = 0.0f;
    #pragma unroll
    for (int i = 0; i < 16; i++) {
        float4 v = row[i];
        s += __expf(v.x - m) + __expf(v.y - m) + __expf(v.z - m) + __expf(v.w - m);
    }

    g_top1[t] = e;
    g_prob[t] = 1.0f / s;

    // within-chunk stable rank
    ((int*)hist)[tid]        = 0;
    ((int*)hist)[tid + 1024] = 0;
    __syncthreads();

    unsigned mm     = __match_any_sync(0xffffffffu, e);
    int      before = __popc(mm & ((1u << lane) - 1u));
    int      leader = __ffs(mm) - 1;
    if (lane == leader) hist[wid][e] = __popc(mm);
    __syncthreads();

    if (tid < N_EXP) {                    // exclusive scan over 32 warps
        int acc = 0;
        #pragma unroll
        for (int w = 0; w < 32; w++) {
            int c = hist[w][tid];
            hist[w][tid] = acc;
            acc += c;
        }
        g_cnt[blockIdx.x][tid] = acc;     // chunk total per expert
    }
    __syncthreads();

    g_rankpart[t] = hist[wid][e] + before;
}

// ---------------------------------------------------------------------------
// Kernel 2: sparse scatter. 8 CTAs x 1024 threads, thread-per-token.
// Each CTA redundantly builds the 8x64 cross-chunk base table (cheap), then
// writes the token's combine weight and mask bit if rank < capacity.
// ---------------------------------------------------------------------------
__global__ void __launch_bounds__(1024) scatter_kernel(float* __restrict__ out,
                                                       long long out_size) {
    __shared__ int base[N_CHUNKS][N_EXP];

    int tid = threadIdx.x;
    if (tid < N_EXP) {                    // 8-step scan per expert
        int acc = 0;
        #pragma unroll
        for (int c = 0; c < N_CHUNKS; c++) {
            base[c][tid] = acc;
            acc += g_cnt[c][tid];
        }
    }
    __syncthreads();

    int t  = blockIdx.x * 1024 + tid;
    int e  = g_top1[t];
    int rk = g_rankpart[t] + base[blockIdx.x][e];

    if (rk < CAPACITY) {
        long long idx = (long long)t * ROW_FLOATS + (long long)e * CAPACITY + rk;
        out[idx] = g_prob[t];             // combine weight
        long long idx2 = C1 + idx;        // sec_mask half (if present)
        if (idx2 < out_size) out[idx2] = 1.0f;
    }
}

extern "C" void kernel_launch(void* const* d_in, const int* in_sizes, int n_in,
                              void* d_out, int out_size) {
    const float* x = (const float*)d_in[0];
    float* out = (float*)d_out;

    route_kernel<<<N_CHUNKS, 1024>>>(x);
    cudaMemsetAsync(d_out, 0, (size_t)out_size * sizeof(float), 0);
    scatter_kernel<<<N_CHUNKS, 1024>>>(out, (long long)out_size);
}

// round 6
// speedup vs baseline: 1.0924x; 1.0924x over previous
#include <cuda_runtime.h>
#include <cuda_bf16.h>

// Top1Router: inputs [8192, 64] fp32.
// capacity = max(even(floor(1.25*8192/64)), 4) = 160
// Output (fp32, concatenated): combine_weights [T,E,C] then sec_mask [T,E,C].
// Strategy: wide softmax/argmax -> narrow stable-rank -> fused zero+fixup fill.

#define T_TOKENS  8192
#define N_EXP     64
#define CAPACITY  160
#define ROW_FLOATS (N_EXP * CAPACITY)     // 10240
#define ROW_F4     (ROW_FLOATS / 4)       // 2560
#define N_CHUNKS   8                      // 8 x 1024 tokens
#define FILL_THREADS 512
#define ROWS_PER_CTA 8

__device__ int   g_top1[T_TOKENS];
__device__ float g_prob[T_TOKENS];
__device__ int   g_rankpart[T_TOKENS];        // within-chunk rank
__device__ int   g_cnt[N_CHUNKS][N_EXP];      // per-chunk per-expert counts

// ---------------------------------------------------------------------------
// Kernel 1: softmax + argmax, thread-per-token, spread wide (64 CTAs).
// Strict > keeps the lowest index on ties, matching jnp.argmax.
// prob(top1) = 1 / sum(exp(x - max)).
// ---------------------------------------------------------------------------
__global__ void __launch_bounds__(128) softmax_kernel(const float* __restrict__ x) {
    int t = blockIdx.x * 128 + threadIdx.x;

    const float4* row = (const float4*)(x + (size_t)t * N_EXP);

    float m = -__FLT_MAX__;
    int   e = 0;
    #pragma unroll
    for (int i = 0; i < 16; i++) {
        float4 v = row[i];
        if (v.x > m) { m = v.x; e = 4 * i + 0; }
        if (v.y > m) { m = v.y; e = 4 * i + 1; }
        if (v.z > m) { m = v.z; e = 4 * i + 2; }
        if (v.w > m) { m = v.w; e = 4 * i + 3; }
    }
    float s = 0.0f;
    #pragma unroll
    for (int i = 0; i < 16; i++) {
        float4 v = row[i];
        s += __expf(v.x - m) + __expf(v.y - m) + __expf(v.z - m) + __expf(v.w - m);
    }

    g_top1[t] = e;
    g_prob[t] = 1.0f / s;
}

// ---------------------------------------------------------------------------
// Kernel 2: within-chunk stable rank. 8 CTAs x 1024 threads; reads only
// g_top1 (32 KB, L2-hot). __match_any + per-warp hist + 64-thread scan.
// ---------------------------------------------------------------------------
__global__ void __launch_bounds__(1024) rank_kernel() {
    __shared__ int hist[32][N_EXP];

    int tid  = threadIdx.x;
    int wid  = tid >> 5;
    int lane = tid & 31;
    int t    = blockIdx.x * 1024 + tid;

    int e = g_top1[t];

    ((int*)hist)[tid]        = 0;
    ((int*)hist)[tid + 1024] = 0;
    __syncthreads();

    unsigned mm     = __match_any_sync(0xffffffffu, e);
    int      before = __popc(mm & ((1u << lane) - 1u));
    int      leader = __ffs(mm) - 1;
    if (lane == leader) hist[wid][e] = __popc(mm);
    __syncthreads();

    if (tid < N_EXP) {                    // exclusive scan over 32 warps
        int acc = 0;
        #pragma unroll
        for (int w = 0; w < 32; w++) {
            int c = hist[w][tid];
            hist[w][tid] = acc;
            acc += c;
        }
        g_cnt[blockIdx.x][tid] = acc;     // chunk total per expert
    }
    __syncthreads();

    g_rankpart[t] = hist[wid][e] + before;
}

// ---------------------------------------------------------------------------
// Kernel 3: fused zero-fill + sparse fixup (one pass over 671 MB).
// Rows 0..8191 = combine (value prob), 8192..16383 = sec_mask (value 1.0).
// Each CTA rebuilds the tiny 8x64 cross-chunk base table, streams float4
// zeros, then the thread owning the special slot rewrites it (same-thread
// program order => no race).
// ---------------------------------------------------------------------------
__global__ void __launch_bounds__(FILL_THREADS) fill_kernel(float* __restrict__ out,
                                                            int n_rows) {
    __shared__ int base[N_CHUNKS][N_EXP];

    int tid = threadIdx.x;
    if (tid < N_EXP) {                    // 8-step scan per expert
        int acc = 0;
        #pragma unroll
        for (int c = 0; c < N_CHUNKS; c++) {
            base[c][tid] = acc;
            acc += g_cnt[c][tid];
        }
    }
    __syncthreads();

    int row0 = blockIdx.x * ROWS_PER_CTA;

    #pragma unroll
    for (int rr = 0; rr < ROWS_PER_CTA; rr++) {
        int r = row0 + rr;
        if (r >= n_rows) break;
        int t = r & (T_TOKENS - 1);

        int e  = g_top1[t];
        int rk = g_rankpart[t] + base[t >> 10][e];
        int sp = (rk < CAPACITY) ? (e * CAPACITY + rk) : -1;   // float offset in row
        float val = (r < T_TOKENS) ? g_prob[t] : 1.0f;

        float4* o = (float4*)(out + (size_t)r * ROW_FLOATS);
        const float4 z = make_float4(0.f, 0.f, 0.f, 0.f);
        #pragma unroll
        for (int it = 0; it < ROW_F4 / FILL_THREADS; it++) {
            __stcs(&o[tid + it * FILL_THREADS], z);
        }
        if (sp >= 0 && tid == ((sp >> 2) & (FILL_THREADS - 1))) {
            ((float*)o)[sp] = val;
        }
    }
}

extern "C" void kernel_launch(void* const* d_in, const int* in_sizes, int n_in,
                              void* d_out, int out_size) {
    const float* x = (const float*)d_in[0];
    float* out = (float*)d_out;

    int n_rows = out_size / ROW_FLOATS;   // 16384 if both halves present

    softmax_kernel<<<T_TOKENS / 128, 128>>>(x);
    rank_kernel<<<N_CHUNKS, 1024>>>();
    fill_kernel<<<(n_rows + ROWS_PER_CTA - 1) / ROWS_PER_CTA, FILL_THREADS>>>(out, n_rows);
}